// round 10
// baseline (speedup 1.0000x reference)
#include <cuda_runtime.h>
#include <math.h>
#include <stdint.h>

// Problem constants (fixed by setup_inputs)
#define NB 2
#define NS 2048
#define ND 768
#define NH 12
#define NDH 64
#define BHN (NB * NH)
#define M_ROWS (NB * NS)      // 4096
#define NQKV (3 * ND)         // 2304

// Scratch (allocation-free rule: __device__ globals).
// R5 lesson: NEVER pass these as host-side kernel args (GB300 ATS reads the
// host shadow silently). Select inside device code via templates.
__device__ alignas(16) float g_Q[BHN * NS * NDH];   // tf32-rounded, Q pre-scaled 0.125
__device__ alignas(16) float g_K[BHN * NS * NDH];   // tf32-rounded
__device__ alignas(16) float g_V[BHN * NS * NDH];   // tf32-rounded
__device__ alignas(16) float g_A[M_ROWS * ND];      // attention out, tf32-rounded
__device__ alignas(16) float g_X[M_ROWS * ND];      // xs, tf32-rounded
__device__ alignas(16) float g_W1[ND * NQKV];       // Wqkv, tf32-rounded
__device__ alignas(16) float g_W2[ND * ND];         // Wout, tf32-rounded

// ---------------------------------------------------------------------------
// Helpers
// ---------------------------------------------------------------------------
__device__ __forceinline__ float to_tf32(float x) {
    uint32_t u;
    asm("cvt.rna.tf32.f32 %0, %1;" : "=r"(u) : "f"(x));
    return __uint_as_float(u);
}

__device__ __forceinline__ uint32_t smem_u32(const void* p) {
    uint32_t a;
    asm("{ .reg .u64 t; cvta.to.shared.u64 t, %1; cvt.u32.u64 %0, t; }" : "=r"(a) : "l"(p));
    return a;
}

__device__ __forceinline__ void cpa16(uint32_t dst, const void* src) {
    asm volatile("cp.async.cg.shared.global [%0], [%1], 16;" :: "r"(dst), "l"(src));
}
#define CP_COMMIT() asm volatile("cp.async.commit_group;")

// D = A(16x8 tf32 row) @ B(8x8 tf32 col) + D, fp32 accum
__device__ __forceinline__ void mma8(float* d, const uint32_t* a, const uint32_t* b) {
    asm volatile(
        "mma.sync.aligned.m16n8k8.row.col.f32.tf32.tf32.f32 "
        "{%0,%1,%2,%3}, {%4,%5,%6,%7}, {%8,%9}, {%0,%1,%2,%3};"
        : "+f"(d[0]), "+f"(d[1]), "+f"(d[2]), "+f"(d[3])
        : "r"(a[0]), "r"(a[1]), "r"(a[2]), "r"(a[3]), "r"(b[0]), "r"(b[1]));
}

// ---------------------------------------------------------------------------
// tf32 pre-round pass: inputs -> scratch (one rounding per element; cp.async
// later moves raw bits so GEMM/attention staging needs no cvt).
// ---------------------------------------------------------------------------
template <int MODE>
__global__ void __launch_bounds__(256) conv_tf32_kernel(const float* __restrict__ src) {
    float* dst = (MODE == 0) ? g_X : (MODE == 1 ? g_W1 : g_W2);
    const int i = blockIdx.x * 256 + threadIdx.x;   // exact grids
    float4 v = reinterpret_cast<const float4*>(src)[i];
    v.x = to_tf32(v.x); v.y = to_tf32(v.y); v.z = to_tf32(v.z); v.w = to_tf32(v.w);
    reinterpret_cast<float4*>(dst)[i] = v;
}

// ---------------------------------------------------------------------------
// GEMM: C[M,N] = A[M,768] @ B[768,N], 128x128 block, K-chunk 32, 8 warps
// (32m x 64n each), 2-stage cp.async double buffering.
// MODE 0: A=g_X, B=g_W1, N=2304, scatter -> g_Q/g_K/g_V (tf32-rounded).
// MODE 1: A=g_A, B=g_W2, N=768 -> out.
// ---------------------------------------------------------------------------
#define AS_STRIDE 36
#define BS_STRIDE 136
#define AS_FL (128 * AS_STRIDE)    // 4608 floats
#define BS_FL (32 * BS_STRIDE)     // 4352 floats
#define GEMM_SMEM ((2 * AS_FL + 2 * BS_FL) * 4)    // 71680 B

template <int MODE>
__global__ void __launch_bounds__(256) gemm_mma_kernel(float* __restrict__ out) {
    extern __shared__ float sm[];
    const float* A = (MODE == 0) ? g_X : g_A;
    const float* B = (MODE == 0) ? g_W1 : g_W2;
    const int ldb = (MODE == 0) ? NQKV : ND;

    const int t = threadIdx.x;
    const int w = t >> 5, lane = t & 31;
    const int lq = lane >> 2, lr = lane & 3;
    const int wm = (w & 3) * 32, wn = (w >> 2) * 64;
    const int m0 = blockIdx.y * 128, n0 = blockIdx.x * 128;
    const uint32_t sb = smem_u32(sm);

    float acc[2][8][4] = {};

    auto stage = [&](int kc, int buf) {
        const uint32_t ab = sb + (uint32_t)(buf * AS_FL) * 4u;
        const uint32_t bb = sb + (uint32_t)(2 * AS_FL + buf * BS_FL) * 4u;
#pragma unroll
        for (int i = 0; i < 4; i++) {           // A: 128x32 = 1024 16B chunks
            const int c = t + i * 256;
            const int row = c >> 3, col = (c & 7) * 4;
            cpa16(ab + (uint32_t)(row * AS_STRIDE + col) * 4u,
                  &A[(size_t)(m0 + row) * ND + kc + col]);
        }
#pragma unroll
        for (int i = 0; i < 4; i++) {           // B: 32x128 = 1024 16B chunks
            const int c = t + i * 256;
            const int row = c >> 5, col = (c & 31) * 4;
            cpa16(bb + (uint32_t)(row * BS_STRIDE + col) * 4u,
                  &B[(size_t)(kc + row) * ldb + n0 + col]);
        }
        CP_COMMIT();
    };

    stage(0, 0);
    for (int it = 0; it < 24; it++) {           // ND/32 chunks
        const int cur = it & 1;
        if (it + 1 < 24) {
            stage((it + 1) * 32, cur ^ 1);
            asm volatile("cp.async.wait_group 1;");
        } else {
            asm volatile("cp.async.wait_group 0;");
        }
        __syncthreads();

        const float* As = sm + cur * AS_FL;
        const float* Bs = sm + 2 * AS_FL + cur * BS_FL;
#pragma unroll
        for (int ks = 0; ks < 4; ks++) {
            const int k = ks * 8;
            uint32_t af[2][4], bf[8][2];
#pragma unroll
            for (int mt = 0; mt < 2; mt++) {
                const int rb = wm + mt * 16 + lq;
                af[mt][0] = __float_as_uint(As[(rb)     * AS_STRIDE + k + lr]);
                af[mt][1] = __float_as_uint(As[(rb + 8) * AS_STRIDE + k + lr]);
                af[mt][2] = __float_as_uint(As[(rb)     * AS_STRIDE + k + lr + 4]);
                af[mt][3] = __float_as_uint(As[(rb + 8) * AS_STRIDE + k + lr + 4]);
            }
#pragma unroll
            for (int nt = 0; nt < 8; nt++) {
                const int cb = wn + nt * 8 + lq;
                bf[nt][0] = __float_as_uint(Bs[(k + lr)     * BS_STRIDE + cb]);
                bf[nt][1] = __float_as_uint(Bs[(k + lr + 4) * BS_STRIDE + cb]);
            }
#pragma unroll
            for (int mt = 0; mt < 2; mt++)
#pragma unroll
                for (int nt = 0; nt < 8; nt++) mma8(acc[mt][nt], af[mt], bf[nt]);
        }
        __syncthreads();   // all warps done with buf `cur` before its overwrite
    }

    // Epilogue. C(mt,nt,q): row = m0+wm+mt*16+lq+(q>>1)*8, col = n0+wn+nt*8+2lr+(q&1)
#pragma unroll
    for (int mt = 0; mt < 2; mt++)
#pragma unroll
        for (int q = 0; q < 4; q++) {
            const int m = m0 + wm + mt * 16 + lq + (q >> 1) * 8;
#pragma unroll
            for (int nt = 0; nt < 8; nt++) {
                const int col = n0 + wn + nt * 8 + 2 * lr + (q & 1);
                const float v = acc[mt][nt][q];
                if (MODE == 0) {
                    const int part = col / ND;               // 0=q 1=k 2=v
                    const int c = col - part * ND;
                    const int h = c % NH, dd = c / NH;
                    const int b = m >> 11, s = m & 2047;
                    float* dst = (part == 0) ? g_Q : (part == 1 ? g_K : g_V);
                    const float scale = (part == 0) ? 0.125f : 1.0f;
                    dst[((size_t)(b * NH + h) * NS + s) * NDH + dd] = to_tf32(v * scale);
                } else {
                    out[(size_t)m * ND + col] = v;
                }
            }
        }
}

// ---------------------------------------------------------------------------
// Flash attention, tf32 mma, cp.async double-buffered K/V tiles.
// Block = (b,h) x 128 Q rows, 8 warps; warp owns 16 full rows. K/V tiles 64.
// SMEM floats: Qs[128][68] | Ks[2][64][68] | Vs[2][64][72] | Ps[128][68]
// ---------------------------------------------------------------------------
#define QS_STRIDE 68
#define KS_STRIDE 68
#define VS_STRIDE 72
#define KS_FL (64 * KS_STRIDE)            // 4352
#define VS_FL (64 * VS_STRIDE)            // 4608
#define OFF_KS (128 * QS_STRIDE)          // 8704
#define OFF_VS (OFF_KS + 2 * KS_FL)       // 17408
#define OFF_PS (OFF_VS + 2 * VS_FL)       // 26624
#define ATTN_SMEM ((OFF_PS + 128 * QS_STRIDE) * 4)   // 141312 B

__global__ void __launch_bounds__(256) attn_mma_kernel() {
    extern __shared__ float sm[];
    float* Qs = sm;
    float* Ps = sm + OFF_PS;

    const int t = threadIdx.x;
    const int w = t >> 5, lane = t & 31;
    const int lq = lane >> 2, lr = lane & 3;
    const int wq = w * 16;
    const int q0 = blockIdx.x * 128;
    const int bh = blockIdx.y;
    const int b = bh / NH, h = bh % NH;
    const uint32_t sb = smem_u32(sm);

    const float* Qg = g_Q + (size_t)bh * NS * NDH;
    const float* Kg = g_K + (size_t)bh * NS * NDH;
    const float* Vg = g_V + (size_t)bh * NS * NDH;

    // Q tile [128][64] via cp.async (already tf32-rounded)
#pragma unroll
    for (int i = 0; i < 8; i++) {                    // 2048 chunks / 256 thr
        const int c = t + i * 256;
        const int row = c >> 4, col = (c & 15) * 4;
        cpa16(sb + (uint32_t)(row * QS_STRIDE + col) * 4u,
              &Qg[(size_t)(q0 + row) * NDH + col]);
    }
    CP_COMMIT();

    auto stage_kv = [&](int k0, int buf) {
        const uint32_t kb = sb + (uint32_t)(OFF_KS + buf * KS_FL) * 4u;
        const uint32_t vb = sb + (uint32_t)(OFF_VS + buf * VS_FL) * 4u;
#pragma unroll
        for (int i = 0; i < 4; i++) {                // 1024 chunks each
            const int c = t + i * 256;
            const int row = c >> 4, col = (c & 15) * 4;
            cpa16(kb + (uint32_t)(row * KS_STRIDE + col) * 4u,
                  &Kg[(size_t)(k0 + row) * NDH + col]);
            cpa16(vb + (uint32_t)(row * VS_STRIDE + col) * 4u,
                  &Vg[(size_t)(k0 + row) * NDH + col]);
        }
        CP_COMMIT();
    };

    stage_kv(0, 0);

    float o[8][4] = {};
    float m0_ = -1e30f, m1_ = -1e30f, l0_ = 0.0f, l1_ = 0.0f;

    for (int it = 0; it < NS / 64; it++) {
        const int cur = it & 1;
        if (it + 1 < NS / 64) {
            stage_kv((it + 1) * 64, cur ^ 1);
            asm volatile("cp.async.wait_group 1;");
        } else {
            asm volatile("cp.async.wait_group 0;");
        }
        __syncthreads();

        const float* Ks = sm + OFF_KS + cur * KS_FL;
        const float* Vs = sm + OFF_VS + cur * VS_FL;

        // S = Q @ K^T : warp tile 16 x 64
        float s[8][4] = {};
#pragma unroll
        for (int ks = 0; ks < 8; ks++) {
            const int k = ks * 8;
            uint32_t af[4], bf[8][2];
            const int rb = wq + lq;
            af[0] = __float_as_uint(Qs[(rb)     * QS_STRIDE + k + lr]);
            af[1] = __float_as_uint(Qs[(rb + 8) * QS_STRIDE + k + lr]);
            af[2] = __float_as_uint(Qs[(rb)     * QS_STRIDE + k + lr + 4]);
            af[3] = __float_as_uint(Qs[(rb + 8) * QS_STRIDE + k + lr + 4]);
#pragma unroll
            for (int nt = 0; nt < 8; nt++) {
                const int nb = nt * 8 + lq;
                bf[nt][0] = __float_as_uint(Ks[nb * KS_STRIDE + k + lr]);
                bf[nt][1] = __float_as_uint(Ks[nb * KS_STRIDE + k + lr + 4]);
            }
#pragma unroll
            for (int nt = 0; nt < 8; nt++) mma8(s[nt], af, bf[nt]);
        }

        // Online softmax (rows r0 = wq+lq: s[*][0..1]; r1 = r0+8: s[*][2..3])
        float mx0 = -1e30f, mx1 = -1e30f;
#pragma unroll
        for (int nt = 0; nt < 8; nt++) {
            mx0 = fmaxf(mx0, fmaxf(s[nt][0], s[nt][1]));
            mx1 = fmaxf(mx1, fmaxf(s[nt][2], s[nt][3]));
        }
        mx0 = fmaxf(mx0, __shfl_xor_sync(0xffffffffu, mx0, 1));
        mx0 = fmaxf(mx0, __shfl_xor_sync(0xffffffffu, mx0, 2));
        mx1 = fmaxf(mx1, __shfl_xor_sync(0xffffffffu, mx1, 1));
        mx1 = fmaxf(mx1, __shfl_xor_sync(0xffffffffu, mx1, 2));
        const float mn0 = fmaxf(m0_, mx0), mn1 = fmaxf(m1_, mx1);
        const float c0 = __expf(m0_ - mn0), c1 = __expf(m1_ - mn1);
        m0_ = mn0; m1_ = mn1;
        float rs0 = 0.0f, rs1 = 0.0f;
#pragma unroll
        for (int nt = 0; nt < 8; nt++) {
            s[nt][0] = __expf(s[nt][0] - mn0); rs0 += s[nt][0];
            s[nt][1] = __expf(s[nt][1] - mn0); rs0 += s[nt][1];
            s[nt][2] = __expf(s[nt][2] - mn1); rs1 += s[nt][2];
            s[nt][3] = __expf(s[nt][3] - mn1); rs1 += s[nt][3];
        }
        rs0 += __shfl_xor_sync(0xffffffffu, rs0, 1);
        rs0 += __shfl_xor_sync(0xffffffffu, rs0, 2);
        rs1 += __shfl_xor_sync(0xffffffffu, rs1, 1);
        rs1 += __shfl_xor_sync(0xffffffffu, rs1, 2);
        l0_ = l0_ * c0 + rs0;
        l1_ = l1_ * c1 + rs1;
#pragma unroll
        for (int nt = 0; nt < 8; nt++) {
            o[nt][0] *= c0; o[nt][1] *= c0; o[nt][2] *= c1; o[nt][3] *= c1;
        }

        // P -> smem (tf32); each warp touches only its own 16 rows
        {
            const int r0 = wq + lq, r1 = r0 + 8;
#pragma unroll
            for (int nt = 0; nt < 8; nt++) {
                const int cc = nt * 8 + 2 * lr;
                Ps[r0 * QS_STRIDE + cc]     = to_tf32(s[nt][0]);
                Ps[r0 * QS_STRIDE + cc + 1] = to_tf32(s[nt][1]);
                Ps[r1 * QS_STRIDE + cc]     = to_tf32(s[nt][2]);
                Ps[r1 * QS_STRIDE + cc + 1] = to_tf32(s[nt][3]);
            }
        }
        __syncwarp();

        // O += P @ V
#pragma unroll
        for (int ks = 0; ks < 8; ks++) {
            const int k = ks * 8;
            uint32_t af[4], bf[8][2];
            const int rb = wq + lq;
            af[0] = __float_as_uint(Ps[(rb)     * QS_STRIDE + k + lr]);
            af[1] = __float_as_uint(Ps[(rb + 8) * QS_STRIDE + k + lr]);
            af[2] = __float_as_uint(Ps[(rb)     * QS_STRIDE + k + lr + 4]);
            af[3] = __float_as_uint(Ps[(rb + 8) * QS_STRIDE + k + lr + 4]);
#pragma unroll
            for (int nt = 0; nt < 8; nt++) {
                const int nb = nt * 8 + lq;
                bf[nt][0] = __float_as_uint(Vs[(k + lr)     * VS_STRIDE + nb]);
                bf[nt][1] = __float_as_uint(Vs[(k + lr + 4) * VS_STRIDE + nb]);
            }
#pragma unroll
            for (int nt = 0; nt < 8; nt++) mma8(o[nt], af, bf[nt]);
        }
        __syncthreads();   // all warps done with buf `cur` before its overwrite
    }

    // Normalize + scatter to g_A [b][s][d*12+h], tf32-rounded for gemm<1>
    const float inv0 = 1.0f / l0_, inv1 = 1.0f / l1_;
    const int s0 = q0 + wq + lq, s1 = s0 + 8;
#pragma unroll
    for (int nt = 0; nt < 8; nt++) {
        const int d0 = nt * 8 + 2 * lr, d1 = d0 + 1;
        g_A[((size_t)b * NS + s0) * ND + d0 * NH + h] = to_tf32(o[nt][0] * inv0);
        g_A[((size_t)b * NS + s0) * ND + d1 * NH + h] = to_tf32(o[nt][1] * inv0);
        g_A[((size_t)b * NS + s1) * ND + d0 * NH + h] = to_tf32(o[nt][2] * inv1);
        g_A[((size_t)b * NS + s1) * ND + d1 * NH + h] = to_tf32(o[nt][3] * inv1);
    }
}

// ---------------------------------------------------------------------------
extern "C" void kernel_launch(void* const* d_in, const int* in_sizes, int n_in,
                              void* d_out, int out_size) {
    const float* xs = nullptr;
    const float* Wqkv = nullptr;
    const float* Wout = nullptr;
    for (int i = 0; i < n_in; i++) {
        const long n = in_sizes[i];
        if (n == (long)M_ROWS * ND)      xs   = (const float*)d_in[i];
        else if (n == (long)ND * NQKV)   Wqkv = (const float*)d_in[i];
        else if (n == (long)ND * ND)     Wout = (const float*)d_in[i];
    }
    float* out = (float*)d_out;

    cudaFuncSetAttribute(gemm_mma_kernel<0>, cudaFuncAttributeMaxDynamicSharedMemorySize, GEMM_SMEM);
    cudaFuncSetAttribute(gemm_mma_kernel<1>, cudaFuncAttributeMaxDynamicSharedMemorySize, GEMM_SMEM);
    cudaFuncSetAttribute(attn_mma_kernel, cudaFuncAttributeMaxDynamicSharedMemorySize, ATTN_SMEM);

    // tf32 pre-round passes (exact grids)
    conv_tf32_kernel<0><<<M_ROWS * ND / 4 / 256, 256>>>(xs);
    conv_tf32_kernel<1><<<ND * NQKV / 4 / 256, 256>>>(Wqkv);
    conv_tf32_kernel<2><<<ND * ND / 4 / 256, 256>>>(Wout);

    // QKV projection: [4096,768] @ [768,2304], scatter epilogue
    gemm_mma_kernel<0><<<dim3(NQKV / 128, M_ROWS / 128), 256, GEMM_SMEM>>>(out);

    // Flash attention (tf32 mma, double-buffered K/V)
    attn_mma_kernel<<<dim3(NS / 128, BHN), 256, ATTN_SMEM>>>();

    // Output projection: [4096,768] @ [768,768] -> d_out
    gemm_mma_kernel<1><<<dim3(ND / 128, M_ROWS / 128), 256, GEMM_SMEM>>>(out);
}

// round 15
// speedup vs baseline: 1.5002x; 1.5002x over previous
#include <cuda_runtime.h>
#include <math.h>
#include <stdint.h>

// Problem constants (fixed by setup_inputs)
#define NB 2
#define NS 2048
#define ND 768
#define NH 12
#define NDH 64
#define BHN (NB * NH)
#define M_ROWS (NB * NS)      // 4096
#define NQKV (3 * ND)         // 2304

// Scratch (allocation-free rule: __device__ globals).
// R5 lesson: NEVER pass these as host-side kernel args (GB300 ATS reads the
// host shadow silently). Select inside device code via templates.
__device__ alignas(16) float g_Q[BHN * NS * NDH];   // tf32-rounded, Q pre-scaled 0.125
__device__ alignas(16) float g_K[BHN * NS * NDH];   // tf32-rounded
__device__ alignas(16) float g_V[BHN * NS * NDH];   // tf32-rounded
__device__ alignas(16) float g_A[M_ROWS * ND];      // attention out, tf32-rounded
__device__ alignas(16) float g_X[M_ROWS * ND];      // xs, tf32-rounded
__device__ alignas(16) float g_W1[ND * NQKV];       // Wqkv, tf32-rounded
__device__ alignas(16) float g_W2[ND * ND];         // Wout, tf32-rounded

// ---------------------------------------------------------------------------
// Helpers
// ---------------------------------------------------------------------------
__device__ __forceinline__ float to_tf32(float x) {
    uint32_t u;
    asm("cvt.rna.tf32.f32 %0, %1;" : "=r"(u) : "f"(x));
    return __uint_as_float(u);
}

__device__ __forceinline__ uint32_t smem_u32(const void* p) {
    uint32_t a;
    asm("{ .reg .u64 t; cvta.to.shared.u64 t, %1; cvt.u32.u64 %0, t; }" : "=r"(a) : "l"(p));
    return a;
}

__device__ __forceinline__ void cpa16(uint32_t dst, const void* src) {
    asm volatile("cp.async.cg.shared.global [%0], [%1], 16;" :: "r"(dst), "l"(src));
}
#define CP_COMMIT() asm volatile("cp.async.commit_group;")

// D = A(16x8 tf32 row) @ B(8x8 tf32 col) + D, fp32 accum
__device__ __forceinline__ void mma8(float* d, const uint32_t* a, const uint32_t* b) {
    asm volatile(
        "mma.sync.aligned.m16n8k8.row.col.f32.tf32.tf32.f32 "
        "{%0,%1,%2,%3}, {%4,%5,%6,%7}, {%8,%9}, {%0,%1,%2,%3};"
        : "+f"(d[0]), "+f"(d[1]), "+f"(d[2]), "+f"(d[3])
        : "r"(a[0]), "r"(a[1]), "r"(a[2]), "r"(a[3]), "r"(b[0]), "r"(b[1]));
}

// ---------------------------------------------------------------------------
// Fused tf32 pre-round pass: xs -> g_X, Wqkv -> g_W1, Wout -> g_W2.
// One rounding per element; cp.async later moves raw bits.
// ---------------------------------------------------------------------------
#define NX4  (M_ROWS * ND / 4)     // 786432
#define NW14 (ND * NQKV / 4)       // 442368
#define NW24 (ND * ND / 4)         // 147456
#define NCONV4 (NX4 + NW14 + NW24) // 1376256 (divisible by 256)

__global__ void __launch_bounds__(256) conv_all_kernel(const float* __restrict__ xs,
                                                       const float* __restrict__ w1,
                                                       const float* __restrict__ w2) {
    int i = blockIdx.x * 256 + threadIdx.x;
    const float4* src;
    float4* dst;
    if (i < NX4)               { src = (const float4*)xs + i;            dst = (float4*)g_X + i; }
    else if (i < NX4 + NW14)   { i -= NX4;  src = (const float4*)w1 + i; dst = (float4*)g_W1 + i; }
    else                       { i -= NX4 + NW14; src = (const float4*)w2 + i; dst = (float4*)g_W2 + i; }
    float4 v = *src;
    v.x = to_tf32(v.x); v.y = to_tf32(v.y); v.z = to_tf32(v.z); v.w = to_tf32(v.w);
    *dst = v;
}

// ---------------------------------------------------------------------------
// GEMM: C[M,N] = A[M,768] @ B[768,N], 128x128 block, K-chunk 32, 8 warps
// (32m x 64n each), 3-stage cp.async pipeline, ONE barrier per iteration.
// MODE 0: A=g_X, B=g_W1, N=2304, scatter -> g_Q/g_K/g_V (tf32-rounded).
// MODE 1: A=g_A, B=g_W2, N=768 -> out.
// ---------------------------------------------------------------------------
#define AS_STRIDE 36
#define BS_STRIDE 136
#define AS_FL (128 * AS_STRIDE)    // 4608 floats
#define BS_FL (32 * BS_STRIDE)     // 4352 floats
#define NCH 24                     // 768/32
#define GEMM_SMEM (3 * (AS_FL + BS_FL) * 4)    // 107520 B

template <int MODE>
__global__ void __launch_bounds__(256) gemm_mma_kernel(float* __restrict__ out) {
    extern __shared__ float sm[];
    const float* A = (MODE == 0) ? g_X : g_A;
    const float* B = (MODE == 0) ? g_W1 : g_W2;
    const int ldb = (MODE == 0) ? NQKV : ND;

    const int t = threadIdx.x;
    const int w = t >> 5, lane = t & 31;
    const int lq = lane >> 2, lr = lane & 3;
    const int wm = (w & 3) * 32, wn = (w >> 2) * 64;
    const int m0 = blockIdx.y * 128, n0 = blockIdx.x * 128;
    const uint32_t sb = smem_u32(sm);

    float acc[2][8][4] = {};

    auto stage = [&](int kc, int buf) {
        const uint32_t ab = sb + (uint32_t)(buf * AS_FL) * 4u;
        const uint32_t bb = sb + (uint32_t)(3 * AS_FL + buf * BS_FL) * 4u;
#pragma unroll
        for (int i = 0; i < 4; i++) {           // A: 128x32 = 1024 16B chunks
            const int c = t + i * 256;
            const int row = c >> 3, col = (c & 7) * 4;
            cpa16(ab + (uint32_t)(row * AS_STRIDE + col) * 4u,
                  &A[(size_t)(m0 + row) * ND + kc + col]);
        }
#pragma unroll
        for (int i = 0; i < 4; i++) {           // B: 32x128 = 1024 16B chunks
            const int c = t + i * 256;
            const int row = c >> 5, col = (c & 31) * 4;
            cpa16(bb + (uint32_t)(row * BS_STRIDE + col) * 4u,
                  &B[(size_t)(kc + row) * ldb + n0 + col]);
        }
        CP_COMMIT();
    };

    stage(0, 0);
    stage(32, 1);
    for (int it = 0; it < NCH; it++) {
        // Wait own copies of group `it` (<=1 younger group outstanding), then
        // barrier makes them CTA-visible AND proves all warps left buf (it-1)%3.
        if (it + 1 < NCH) asm volatile("cp.async.wait_group 1;");
        else              asm volatile("cp.async.wait_group 0;");
        __syncthreads();
        if (it + 2 < NCH) stage((it + 2) * 32, (it + 2) % 3);

        const int cur = it % 3;
        const float* As = sm + cur * AS_FL;
        const float* Bs = sm + 3 * AS_FL + cur * BS_FL;
#pragma unroll
        for (int ks = 0; ks < 4; ks++) {
            const int k = ks * 8;
            uint32_t af[2][4], bf[8][2];
#pragma unroll
            for (int mt = 0; mt < 2; mt++) {
                const int rb = wm + mt * 16 + lq;
                af[mt][0] = __float_as_uint(As[(rb)     * AS_STRIDE + k + lr]);
                af[mt][1] = __float_as_uint(As[(rb + 8) * AS_STRIDE + k + lr]);
                af[mt][2] = __float_as_uint(As[(rb)     * AS_STRIDE + k + lr + 4]);
                af[mt][3] = __float_as_uint(As[(rb + 8) * AS_STRIDE + k + lr + 4]);
            }
#pragma unroll
            for (int nt = 0; nt < 8; nt++) {
                const int cb = wn + nt * 8 + lq;
                bf[nt][0] = __float_as_uint(Bs[(k + lr)     * BS_STRIDE + cb]);
                bf[nt][1] = __float_as_uint(Bs[(k + lr + 4) * BS_STRIDE + cb]);
            }
#pragma unroll
            for (int mt = 0; mt < 2; mt++)
#pragma unroll
                for (int nt = 0; nt < 8; nt++) mma8(acc[mt][nt], af[mt], bf[nt]);
        }
    }

    // Epilogue. C(mt,nt,q): row = m0+wm+mt*16+lq+(q>>1)*8, col = n0+wn+nt*8+2lr+(q&1)
#pragma unroll
    for (int mt = 0; mt < 2; mt++)
#pragma unroll
        for (int q = 0; q < 4; q++) {
            const int m = m0 + wm + mt * 16 + lq + (q >> 1) * 8;
#pragma unroll
            for (int nt = 0; nt < 8; nt++) {
                const int col = n0 + wn + nt * 8 + 2 * lr + (q & 1);
                const float v = acc[mt][nt][q];
                if (MODE == 0) {
                    const int part = col / ND;               // 0=q 1=k 2=v
                    const int c = col - part * ND;
                    const int h = c % NH, dd = c / NH;
                    const int b = m >> 11, s = m & 2047;
                    float* dst = (part == 0) ? g_Q : (part == 1 ? g_K : g_V);
                    const float scale = (part == 0) ? 0.125f : 1.0f;
                    dst[((size_t)(b * NH + h) * NS + s) * NDH + dd] = to_tf32(v * scale);
                } else {
                    out[(size_t)m * ND + col] = v;
                }
            }
        }
}

// ---------------------------------------------------------------------------
// Flash attention, tf32 mma. R10 lesson: occupancy beats intra-CTA prefetch.
// Block = (b,h) x 64 Q rows, 128 threads (4 warps x 16 rows), single-buffered
// K/V tiles of 64, cp.async loads. SMEM 70.6KB -> 3 CTAs/SM.
// SMEM floats: Qs[64][68] | Ks[64][68] | Vs[64][72] | Ps[64][68]
// ---------------------------------------------------------------------------
#define QS_STRIDE 68
#define KS_STRIDE 68
#define VS_STRIDE 72
#define OFF_KS (64 * QS_STRIDE)           // 4352
#define OFF_VS (OFF_KS + 64 * KS_STRIDE)  // 8704
#define OFF_PS (OFF_VS + 64 * VS_STRIDE)  // 13312
#define ATTN_SMEM ((OFF_PS + 64 * QS_STRIDE) * 4)   // 70656 B

__global__ void __launch_bounds__(128) attn_mma_kernel() {
    extern __shared__ float sm[];
    float* Qs = sm;
    float* Ks = sm + OFF_KS;
    float* Vs = sm + OFF_VS;
    float* Ps = sm + OFF_PS;

    const int t = threadIdx.x;
    const int w = t >> 5, lane = t & 31;
    const int lq = lane >> 2, lr = lane & 3;
    const int wq = w * 16;                 // warp's 16 q rows (of 64)
    const int q0 = blockIdx.x * 64;
    const int bh = blockIdx.y;
    const int b = bh / NH, h = bh % NH;
    const uint32_t sb = smem_u32(sm);

    const float* Qg = g_Q + (size_t)bh * NS * NDH;
    const float* Kg = g_K + (size_t)bh * NS * NDH;
    const float* Vg = g_V + (size_t)bh * NS * NDH;

    // Q tile [64][64] via cp.async (already tf32-rounded): 1024 chunks / 128 thr
#pragma unroll
    for (int i = 0; i < 8; i++) {
        const int c = t + i * 128;
        const int row = c >> 4, col = (c & 15) * 4;
        cpa16(sb + (uint32_t)(row * QS_STRIDE + col) * 4u,
              &Qg[(size_t)(q0 + row) * NDH + col]);
    }
    CP_COMMIT();

    float o[8][4] = {};
    float m0_ = -1e30f, m1_ = -1e30f, l0_ = 0.0f, l1_ = 0.0f;

    for (int k0 = 0; k0 < NS; k0 += 64) {
        __syncthreads();   // prior iter's K/V readers done before overwrite
        {
            const uint32_t kb = sb + (uint32_t)OFF_KS * 4u;
            const uint32_t vb = sb + (uint32_t)OFF_VS * 4u;
#pragma unroll
            for (int i = 0; i < 8; i++) {          // 1024 chunks each
                const int c = t + i * 128;
                const int row = c >> 4, col = (c & 15) * 4;
                cpa16(kb + (uint32_t)(row * KS_STRIDE + col) * 4u,
                      &Kg[(size_t)(k0 + row) * NDH + col]);
                cpa16(vb + (uint32_t)(row * VS_STRIDE + col) * 4u,
                      &Vg[(size_t)(k0 + row) * NDH + col]);
            }
            CP_COMMIT();
        }
        asm volatile("cp.async.wait_group 0;");
        __syncthreads();

        // S = Q @ K^T : warp tile 16 x 64
        float s[8][4] = {};
#pragma unroll
        for (int ks = 0; ks < 8; ks++) {
            const int k = ks * 8;
            uint32_t af[4], bf[8][2];
            const int rb = wq + lq;
            af[0] = __float_as_uint(Qs[(rb)     * QS_STRIDE + k + lr]);
            af[1] = __float_as_uint(Qs[(rb + 8) * QS_STRIDE + k + lr]);
            af[2] = __float_as_uint(Qs[(rb)     * QS_STRIDE + k + lr + 4]);
            af[3] = __float_as_uint(Qs[(rb + 8) * QS_STRIDE + k + lr + 4]);
#pragma unroll
            for (int nt = 0; nt < 8; nt++) {
                const int nb = nt * 8 + lq;
                bf[nt][0] = __float_as_uint(Ks[nb * KS_STRIDE + k + lr]);
                bf[nt][1] = __float_as_uint(Ks[nb * KS_STRIDE + k + lr + 4]);
            }
#pragma unroll
            for (int nt = 0; nt < 8; nt++) mma8(s[nt], af, bf[nt]);
        }

        // Online softmax (rows r0 = wq+lq: s[*][0..1]; r1 = r0+8: s[*][2..3])
        float mx0 = -1e30f, mx1 = -1e30f;
#pragma unroll
        for (int nt = 0; nt < 8; nt++) {
            mx0 = fmaxf(mx0, fmaxf(s[nt][0], s[nt][1]));
            mx1 = fmaxf(mx1, fmaxf(s[nt][2], s[nt][3]));
        }
        mx0 = fmaxf(mx0, __shfl_xor_sync(0xffffffffu, mx0, 1));
        mx0 = fmaxf(mx0, __shfl_xor_sync(0xffffffffu, mx0, 2));
        mx1 = fmaxf(mx1, __shfl_xor_sync(0xffffffffu, mx1, 1));
        mx1 = fmaxf(mx1, __shfl_xor_sync(0xffffffffu, mx1, 2));
        const float mn0 = fmaxf(m0_, mx0), mn1 = fmaxf(m1_, mx1);
        const float c0 = __expf(m0_ - mn0), c1 = __expf(m1_ - mn1);
        m0_ = mn0; m1_ = mn1;
        float rs0 = 0.0f, rs1 = 0.0f;
#pragma unroll
        for (int nt = 0; nt < 8; nt++) {
            s[nt][0] = __expf(s[nt][0] - mn0); rs0 += s[nt][0];
            s[nt][1] = __expf(s[nt][1] - mn0); rs0 += s[nt][1];
            s[nt][2] = __expf(s[nt][2] - mn1); rs1 += s[nt][2];
            s[nt][3] = __expf(s[nt][3] - mn1); rs1 += s[nt][3];
        }
        rs0 += __shfl_xor_sync(0xffffffffu, rs0, 1);
        rs0 += __shfl_xor_sync(0xffffffffu, rs0, 2);
        rs1 += __shfl_xor_sync(0xffffffffu, rs1, 1);
        rs1 += __shfl_xor_sync(0xffffffffu, rs1, 2);
        l0_ = l0_ * c0 + rs0;
        l1_ = l1_ * c1 + rs1;
#pragma unroll
        for (int nt = 0; nt < 8; nt++) {
            o[nt][0] *= c0; o[nt][1] *= c0; o[nt][2] *= c1; o[nt][3] *= c1;
        }

        // P -> smem (tf32); each warp touches only its own 16 rows
        {
            const int r0 = wq + lq, r1 = r0 + 8;
#pragma unroll
            for (int nt = 0; nt < 8; nt++) {
                const int cc = nt * 8 + 2 * lr;
                Ps[r0 * QS_STRIDE + cc]     = to_tf32(s[nt][0]);
                Ps[r0 * QS_STRIDE + cc + 1] = to_tf32(s[nt][1]);
                Ps[r1 * QS_STRIDE + cc]     = to_tf32(s[nt][2]);
                Ps[r1 * QS_STRIDE + cc + 1] = to_tf32(s[nt][3]);
            }
        }
        __syncwarp();

        // O += P @ V
#pragma unroll
        for (int ks = 0; ks < 8; ks++) {
            const int k = ks * 8;
            uint32_t af[4], bf[8][2];
            const int rb = wq + lq;
            af[0] = __float_as_uint(Ps[(rb)     * QS_STRIDE + k + lr]);
            af[1] = __float_as_uint(Ps[(rb + 8) * QS_STRIDE + k + lr]);
            af[2] = __float_as_uint(Ps[(rb)     * QS_STRIDE + k + lr + 4]);
            af[3] = __float_as_uint(Ps[(rb + 8) * QS_STRIDE + k + lr + 4]);
#pragma unroll
            for (int nt = 0; nt < 8; nt++) {
                const int nb = nt * 8 + lq;
                bf[nt][0] = __float_as_uint(Vs[(k + lr)     * VS_STRIDE + nb]);
                bf[nt][1] = __float_as_uint(Vs[(k + lr + 4) * VS_STRIDE + nb]);
            }
#pragma unroll
            for (int nt = 0; nt < 8; nt++) mma8(o[nt], af, bf[nt]);
        }
    }

    // Normalize + scatter to g_A [b][s][d*12+h], tf32-rounded for gemm<1>
    const float inv0 = 1.0f / l0_, inv1 = 1.0f / l1_;
    const int s0 = q0 + wq + lq, s1 = s0 + 8;
#pragma unroll
    for (int nt = 0; nt < 8; nt++) {
        const int d0 = nt * 8 + 2 * lr, d1 = d0 + 1;
        g_A[((size_t)b * NS + s0) * ND + d0 * NH + h] = to_tf32(o[nt][0] * inv0);
        g_A[((size_t)b * NS + s0) * ND + d1 * NH + h] = to_tf32(o[nt][1] * inv0);
        g_A[((size_t)b * NS + s1) * ND + d0 * NH + h] = to_tf32(o[nt][2] * inv1);
        g_A[((size_t)b * NS + s1) * ND + d1 * NH + h] = to_tf32(o[nt][3] * inv1);
    }
}

// ---------------------------------------------------------------------------
extern "C" void kernel_launch(void* const* d_in, const int* in_sizes, int n_in,
                              void* d_out, int out_size) {
    const float* xs = nullptr;
    const float* Wqkv = nullptr;
    const float* Wout = nullptr;
    for (int i = 0; i < n_in; i++) {
        const long n = in_sizes[i];
        if (n == (long)M_ROWS * ND)      xs   = (const float*)d_in[i];
        else if (n == (long)ND * NQKV)   Wqkv = (const float*)d_in[i];
        else if (n == (long)ND * ND)     Wout = (const float*)d_in[i];
    }
    float* out = (float*)d_out;

    cudaFuncSetAttribute(gemm_mma_kernel<0>, cudaFuncAttributeMaxDynamicSharedMemorySize, GEMM_SMEM);
    cudaFuncSetAttribute(gemm_mma_kernel<1>, cudaFuncAttributeMaxDynamicSharedMemorySize, GEMM_SMEM);
    cudaFuncSetAttribute(attn_mma_kernel, cudaFuncAttributeMaxDynamicSharedMemorySize, ATTN_SMEM);

    // Fused tf32 pre-round pass
    conv_all_kernel<<<NCONV4 / 256, 256>>>(xs, Wqkv, Wout);

    // QKV projection: [4096,768] @ [768,2304], scatter epilogue
    gemm_mma_kernel<0><<<dim3(NQKV / 128, M_ROWS / 128), 256, GEMM_SMEM>>>(out);

    // Flash attention (tf32 mma, 64-q blocks, 3 CTAs/SM)
    attn_mma_kernel<<<dim3(NS / 64, BHN), 128, ATTN_SMEM>>>();

    // Output projection: [4096,768] @ [768,768] -> d_out
    gemm_mma_kernel<1><<<dim3(ND / 128, M_ROWS / 128), 256, GEMM_SMEM>>>(out);
}

// round 16
// speedup vs baseline: 1.6001x; 1.0666x over previous
#include <cuda_runtime.h>
#include <math.h>
#include <stdint.h>

// Problem constants (fixed by setup_inputs)
#define NB 2
#define NS 2048
#define ND 768
#define NH 12
#define NDH 64
#define BHN (NB * NH)
#define M_ROWS (NB * NS)      // 4096
#define NQKV (3 * ND)         // 2304

// Scratch (allocation-free rule: __device__ globals).
// R5 lesson: NEVER pass these as host-side kernel args (GB300 ATS reads the
// host shadow silently). Select inside device code via templates.
__device__ alignas(16) float g_Q[BHN * NS * NDH];   // tf32-rounded, Q pre-scaled 0.125
__device__ alignas(16) float g_K[BHN * NS * NDH];   // tf32-rounded
__device__ alignas(16) float g_V[BHN * NS * NDH];   // tf32-rounded
__device__ alignas(16) float g_A[M_ROWS * ND];      // attention out, tf32-rounded
__device__ alignas(16) float g_X[M_ROWS * ND];      // xs, tf32-rounded
__device__ alignas(16) float g_W1[ND * NQKV];       // Wqkv, tf32-rounded
__device__ alignas(16) float g_W2[ND * ND];         // Wout, tf32-rounded

// ---------------------------------------------------------------------------
// Helpers
// ---------------------------------------------------------------------------
__device__ __forceinline__ float to_tf32(float x) {
    uint32_t u;
    asm("cvt.rna.tf32.f32 %0, %1;" : "=r"(u) : "f"(x));
    return __uint_as_float(u);
}

__device__ __forceinline__ uint32_t smem_u32(const void* p) {
    uint32_t a;
    asm("{ .reg .u64 t; cvta.to.shared.u64 t, %1; cvt.u32.u64 %0, t; }" : "=r"(a) : "l"(p));
    return a;
}

__device__ __forceinline__ void cpa16(uint32_t dst, const void* src) {
    asm volatile("cp.async.cg.shared.global [%0], [%1], 16;" :: "r"(dst), "l"(src));
}
#define CP_COMMIT() asm volatile("cp.async.commit_group;")

// D = A(16x8 tf32 row) @ B(8x8 tf32 col) + D, fp32 accum
__device__ __forceinline__ void mma8(float* d, const uint32_t* a, const uint32_t* b) {
    asm volatile(
        "mma.sync.aligned.m16n8k8.row.col.f32.tf32.tf32.f32 "
        "{%0,%1,%2,%3}, {%4,%5,%6,%7}, {%8,%9}, {%0,%1,%2,%3};"
        : "+f"(d[0]), "+f"(d[1]), "+f"(d[2]), "+f"(d[3])
        : "r"(a[0]), "r"(a[1]), "r"(a[2]), "r"(a[3]), "r"(b[0]), "r"(b[1]));
}

// ---------------------------------------------------------------------------
// Fused tf32 pre-round pass: xs -> g_X, Wqkv -> g_W1, Wout -> g_W2.
// ---------------------------------------------------------------------------
#define NX4  (M_ROWS * ND / 4)     // 786432
#define NW14 (ND * NQKV / 4)       // 442368
#define NW24 (ND * ND / 4)         // 147456
#define NCONV4 (NX4 + NW14 + NW24) // 1376256 (divisible by 256)

__global__ void __launch_bounds__(256) conv_all_kernel(const float* __restrict__ xs,
                                                       const float* __restrict__ w1,
                                                       const float* __restrict__ w2) {
    int i = blockIdx.x * 256 + threadIdx.x;
    const float4* src;
    float4* dst;
    if (i < NX4)               { src = (const float4*)xs + i;            dst = (float4*)g_X + i; }
    else if (i < NX4 + NW14)   { i -= NX4;  src = (const float4*)w1 + i; dst = (float4*)g_W1 + i; }
    else                       { i -= NX4 + NW14; src = (const float4*)w2 + i; dst = (float4*)g_W2 + i; }
    float4 v = *src;
    v.x = to_tf32(v.x); v.y = to_tf32(v.y); v.z = to_tf32(v.z); v.w = to_tf32(v.w);
    *dst = v;
}

// ---------------------------------------------------------------------------
// GEMM: C[M,N] = A[M,768] @ B[768,N], 128x128 block, K-chunk 32, 8 warps
// (32m x 64n each). 2-stage cp.async pipeline, ONE barrier per iteration.
// R15 lesson: 3-stage smem (107KB) capped occupancy at 1 CTA/SM (2 warps/
// SMSP) -> latency-bound. 2-stage (71.7KB) + <=128 regs gives 2 CTAs/SM.
// MODE 0: A=g_X, B=g_W1, N=2304, scatter -> g_Q/g_K/g_V (tf32-rounded).
// MODE 1: A=g_A, B=g_W2, N=768 -> out.
// ---------------------------------------------------------------------------
#define AS_STRIDE 36
#define BS_STRIDE 136
#define AS_FL (128 * AS_STRIDE)    // 4608 floats
#define BS_FL (32 * BS_STRIDE)     // 4352 floats
#define NCH 24                     // 768/32
#define GEMM_SMEM (2 * (AS_FL + BS_FL) * 4)    // 71680 B

template <int MODE>
__global__ void __launch_bounds__(256, 2) gemm_mma_kernel(float* __restrict__ out) {
    extern __shared__ float sm[];
    const float* A = (MODE == 0) ? g_X : g_A;
    const float* B = (MODE == 0) ? g_W1 : g_W2;
    const int ldb = (MODE == 0) ? NQKV : ND;

    const int t = threadIdx.x;
    const int w = t >> 5, lane = t & 31;
    const int lq = lane >> 2, lr = lane & 3;
    const int wm = (w & 3) * 32, wn = (w >> 2) * 64;
    const int m0 = blockIdx.y * 128, n0 = blockIdx.x * 128;
    const uint32_t sb = smem_u32(sm);

    float acc[2][8][4] = {};

    auto stage = [&](int kc, int buf) {
        const uint32_t ab = sb + (uint32_t)(buf * AS_FL) * 4u;
        const uint32_t bb = sb + (uint32_t)(2 * AS_FL + buf * BS_FL) * 4u;
#pragma unroll
        for (int i = 0; i < 4; i++) {           // A: 128x32 = 1024 16B chunks
            const int c = t + i * 256;
            const int row = c >> 3, col = (c & 7) * 4;
            cpa16(ab + (uint32_t)(row * AS_STRIDE + col) * 4u,
                  &A[(size_t)(m0 + row) * ND + kc + col]);
        }
#pragma unroll
        for (int i = 0; i < 4; i++) {           // B: 32x128 = 1024 16B chunks
            const int c = t + i * 256;
            const int row = c >> 5, col = (c & 31) * 4;
            cpa16(bb + (uint32_t)(row * BS_STRIDE + col) * 4u,
                  &B[(size_t)(kc + row) * ldb + n0 + col]);
        }
        CP_COMMIT();
    };

    stage(0, 0);
    for (int it = 0; it < NCH; it++) {
        // Wait group `it` (the copy issued last iteration had a full compute
        // phase to land). Barrier makes it CTA-visible AND proves all warps
        // finished reading buf (it-1)&1 before stage(it+1) overwrites it.
        asm volatile("cp.async.wait_group 0;");
        __syncthreads();
        if (it + 1 < NCH) stage((it + 1) * 32, (it + 1) & 1);

        const int cur = it & 1;
        const float* As = sm + cur * AS_FL;
        const float* Bs = sm + 2 * AS_FL + cur * BS_FL;
#pragma unroll
        for (int ks = 0; ks < 4; ks++) {
            const int k = ks * 8;
            uint32_t af[2][4], bf[8][2];
#pragma unroll
            for (int mt = 0; mt < 2; mt++) {
                const int rb = wm + mt * 16 + lq;
                af[mt][0] = __float_as_uint(As[(rb)     * AS_STRIDE + k + lr]);
                af[mt][1] = __float_as_uint(As[(rb + 8) * AS_STRIDE + k + lr]);
                af[mt][2] = __float_as_uint(As[(rb)     * AS_STRIDE + k + lr + 4]);
                af[mt][3] = __float_as_uint(As[(rb + 8) * AS_STRIDE + k + lr + 4]);
            }
#pragma unroll
            for (int nt = 0; nt < 8; nt++) {
                const int cb = wn + nt * 8 + lq;
                bf[nt][0] = __float_as_uint(Bs[(k + lr)     * BS_STRIDE + cb]);
                bf[nt][1] = __float_as_uint(Bs[(k + lr + 4) * BS_STRIDE + cb]);
            }
#pragma unroll
            for (int mt = 0; mt < 2; mt++)
#pragma unroll
                for (int nt = 0; nt < 8; nt++) mma8(acc[mt][nt], af[mt], bf[nt]);
        }
    }

    // Epilogue. C(mt,nt,q): row = m0+wm+mt*16+lq+(q>>1)*8, col = n0+wn+nt*8+2lr+(q&1)
#pragma unroll
    for (int mt = 0; mt < 2; mt++)
#pragma unroll
        for (int q = 0; q < 4; q++) {
            const int m = m0 + wm + mt * 16 + lq + (q >> 1) * 8;
#pragma unroll
            for (int nt = 0; nt < 8; nt++) {
                const int col = n0 + wn + nt * 8 + 2 * lr + (q & 1);
                const float v = acc[mt][nt][q];
                if (MODE == 0) {
                    const int part = col / ND;               // 0=q 1=k 2=v
                    const int c = col - part * ND;
                    const int h = c % NH, dd = c / NH;
                    const int b = m >> 11, s = m & 2047;
                    float* dst = (part == 0) ? g_Q : (part == 1 ? g_K : g_V);
                    const float scale = (part == 0) ? 0.125f : 1.0f;
                    dst[((size_t)(b * NH + h) * NS + s) * NDH + dd] = to_tf32(v * scale);
                } else {
                    out[(size_t)m * ND + col] = v;
                }
            }
        }
}

// ---------------------------------------------------------------------------
// Flash attention, tf32 mma. R10 lesson: occupancy beats intra-CTA prefetch.
// R15 -> R16: alias P onto the K tile (K dead after QK^T) to cut SMEM
// 70.6KB -> 53.2KB => 4 CTAs/SM (16 warps). Costs one extra barrier per
// k-tile between the last K read and the P write.
// Block = (b,h) x 64 Q rows, 128 threads (4 warps x 16 rows), K/V tiles 64.
// SMEM floats: Qs[64][68] | Ks[64][68] (=Ps) | Vs[64][72]
// ---------------------------------------------------------------------------
#define QS_STRIDE 68
#define KS_STRIDE 68
#define VS_STRIDE 72
#define OFF_KS (64 * QS_STRIDE)           // 4352
#define OFF_VS (OFF_KS + 64 * KS_STRIDE)  // 8704
#define ATTN_SMEM ((OFF_VS + 64 * VS_STRIDE) * 4)   // 53248 B

__global__ void __launch_bounds__(128, 4) attn_mma_kernel() {
    extern __shared__ float sm[];
    float* Qs = sm;
    float* Ks = sm + OFF_KS;
    float* Vs = sm + OFF_VS;
    float* Ps = Ks;                        // alias: K tile reused for P

    const int t = threadIdx.x;
    const int w = t >> 5, lane = t & 31;
    const int lq = lane >> 2, lr = lane & 3;
    const int wq = w * 16;                 // warp's 16 q rows (of 64)
    const int q0 = blockIdx.x * 64;
    const int bh = blockIdx.y;
    const int b = bh / NH, h = bh % NH;
    const uint32_t sb = smem_u32(sm);

    const float* Qg = g_Q + (size_t)bh * NS * NDH;
    const float* Kg = g_K + (size_t)bh * NS * NDH;
    const float* Vg = g_V + (size_t)bh * NS * NDH;

    // Q tile [64][64] via cp.async (already tf32-rounded): 1024 chunks / 128 thr
#pragma unroll
    for (int i = 0; i < 8; i++) {
        const int c = t + i * 128;
        const int row = c >> 4, col = (c & 15) * 4;
        cpa16(sb + (uint32_t)(row * QS_STRIDE + col) * 4u,
              &Qg[(size_t)(q0 + row) * NDH + col]);
    }
    CP_COMMIT();

    float o[8][4] = {};
    float m0_ = -1e30f, m1_ = -1e30f, l0_ = 0.0f, l1_ = 0.0f;

    for (int k0 = 0; k0 < NS; k0 += 64) {
        __syncthreads();   // prior iter's P/V readers done before K/V overwrite
        {
            const uint32_t kb = sb + (uint32_t)OFF_KS * 4u;
            const uint32_t vb = sb + (uint32_t)OFF_VS * 4u;
#pragma unroll
            for (int i = 0; i < 8; i++) {          // 1024 chunks each
                const int c = t + i * 128;
                const int row = c >> 4, col = (c & 15) * 4;
                cpa16(kb + (uint32_t)(row * KS_STRIDE + col) * 4u,
                      &Kg[(size_t)(k0 + row) * NDH + col]);
                cpa16(vb + (uint32_t)(row * VS_STRIDE + col) * 4u,
                      &Vg[(size_t)(k0 + row) * NDH + col]);
            }
            CP_COMMIT();
        }
        asm volatile("cp.async.wait_group 0;");
        __syncthreads();

        // S = Q @ K^T : warp tile 16 x 64
        float s[8][4] = {};
#pragma unroll
        for (int ks = 0; ks < 8; ks++) {
            const int k = ks * 8;
            uint32_t af[4], bf[8][2];
            const int rb = wq + lq;
            af[0] = __float_as_uint(Qs[(rb)     * QS_STRIDE + k + lr]);
            af[1] = __float_as_uint(Qs[(rb + 8) * QS_STRIDE + k + lr]);
            af[2] = __float_as_uint(Qs[(rb)     * QS_STRIDE + k + lr + 4]);
            af[3] = __float_as_uint(Qs[(rb + 8) * QS_STRIDE + k + lr + 4]);
#pragma unroll
            for (int nt = 0; nt < 8; nt++) {
                const int nb = nt * 8 + lq;
                bf[nt][0] = __float_as_uint(Ks[nb * KS_STRIDE + k + lr]);
                bf[nt][1] = __float_as_uint(Ks[nb * KS_STRIDE + k + lr + 4]);
            }
#pragma unroll
            for (int nt = 0; nt < 8; nt++) mma8(s[nt], af, bf[nt]);
        }

        // Online softmax (rows r0 = wq+lq: s[*][0..1]; r1 = r0+8: s[*][2..3])
        float mx0 = -1e30f, mx1 = -1e30f;
#pragma unroll
        for (int nt = 0; nt < 8; nt++) {
            mx0 = fmaxf(mx0, fmaxf(s[nt][0], s[nt][1]));
            mx1 = fmaxf(mx1, fmaxf(s[nt][2], s[nt][3]));
        }
        mx0 = fmaxf(mx0, __shfl_xor_sync(0xffffffffu, mx0, 1));
        mx0 = fmaxf(mx0, __shfl_xor_sync(0xffffffffu, mx0, 2));
        mx1 = fmaxf(mx1, __shfl_xor_sync(0xffffffffu, mx1, 1));
        mx1 = fmaxf(mx1, __shfl_xor_sync(0xffffffffu, mx1, 2));
        const float mn0 = fmaxf(m0_, mx0), mn1 = fmaxf(m1_, mx1);
        const float c0 = __expf(m0_ - mn0), c1 = __expf(m1_ - mn1);
        m0_ = mn0; m1_ = mn1;
        float rs0 = 0.0f, rs1 = 0.0f;
#pragma unroll
        for (int nt = 0; nt < 8; nt++) {
            s[nt][0] = __expf(s[nt][0] - mn0); rs0 += s[nt][0];
            s[nt][1] = __expf(s[nt][1] - mn0); rs0 += s[nt][1];
            s[nt][2] = __expf(s[nt][2] - mn1); rs1 += s[nt][2];
            s[nt][3] = __expf(s[nt][3] - mn1); rs1 += s[nt][3];
        }
        rs0 += __shfl_xor_sync(0xffffffffu, rs0, 1);
        rs0 += __shfl_xor_sync(0xffffffffu, rs0, 2);
        rs1 += __shfl_xor_sync(0xffffffffu, rs1, 1);
        rs1 += __shfl_xor_sync(0xffffffffu, rs1, 2);
        l0_ = l0_ * c0 + rs0;
        l1_ = l1_ * c1 + rs1;
#pragma unroll
        for (int nt = 0; nt < 8; nt++) {
            o[nt][0] *= c0; o[nt][1] *= c0; o[nt][2] *= c1; o[nt][3] *= c1;
        }

        // All warps must be done reading K fragments before P overwrites them
        __syncthreads();

        // P -> smem (tf32) into the K region; each warp writes only its own rows
        {
            const int r0 = wq + lq, r1 = r0 + 8;
#pragma unroll
            for (int nt = 0; nt < 8; nt++) {
                const int cc = nt * 8 + 2 * lr;
                Ps[r0 * KS_STRIDE + cc]     = to_tf32(s[nt][0]);
                Ps[r0 * KS_STRIDE + cc + 1] = to_tf32(s[nt][1]);
                Ps[r1 * KS_STRIDE + cc]     = to_tf32(s[nt][2]);
                Ps[r1 * KS_STRIDE + cc + 1] = to_tf32(s[nt][3]);
            }
        }
        __syncwarp();   // PV reads only this warp's own P rows

        // O += P @ V
#pragma unroll
        for (int ks = 0; ks < 8; ks++) {
            const int k = ks * 8;
            uint32_t af[4], bf[8][2];
            const int rb = wq + lq;
            af[0] = __float_as_uint(Ps[(rb)     * KS_STRIDE + k + lr]);
            af[1] = __float_as_uint(Ps[(rb + 8) * KS_STRIDE + k + lr]);
            af[2] = __float_as_uint(Ps[(rb)     * KS_STRIDE + k + lr + 4]);
            af[3] = __float_as_uint(Ps[(rb + 8) * KS_STRIDE + k + lr + 4]);
#pragma unroll
            for (int nt = 0; nt < 8; nt++) {
                const int nb = nt * 8 + lq;
                bf[nt][0] = __float_as_uint(Vs[(k + lr)     * VS_STRIDE + nb]);
                bf[nt][1] = __float_as_uint(Vs[(k + lr + 4) * VS_STRIDE + nb]);
            }
#pragma unroll
            for (int nt = 0; nt < 8; nt++) mma8(o[nt], af, bf[nt]);
        }
    }

    // Normalize + scatter to g_A [b][s][d*12+h], tf32-rounded for gemm<1>
    const float inv0 = 1.0f / l0_, inv1 = 1.0f / l1_;
    const int s0 = q0 + wq + lq, s1 = s0 + 8;
#pragma unroll
    for (int nt = 0; nt < 8; nt++) {
        const int d0 = nt * 8 + 2 * lr, d1 = d0 + 1;
        g_A[((size_t)b * NS + s0) * ND + d0 * NH + h] = to_tf32(o[nt][0] * inv0);
        g_A[((size_t)b * NS + s0) * ND + d1 * NH + h] = to_tf32(o[nt][1] * inv0);
        g_A[((size_t)b * NS + s1) * ND + d0 * NH + h] = to_tf32(o[nt][2] * inv1);
        g_A[((size_t)b * NS + s1) * ND + d1 * NH + h] = to_tf32(o[nt][3] * inv1);
    }
}

// ---------------------------------------------------------------------------
extern "C" void kernel_launch(void* const* d_in, const int* in_sizes, int n_in,
                              void* d_out, int out_size) {
    const float* xs = nullptr;
    const float* Wqkv = nullptr;
    const float* Wout = nullptr;
    for (int i = 0; i < n_in; i++) {
        const long n = in_sizes[i];
        if (n == (long)M_ROWS * ND)      xs   = (const float*)d_in[i];
        else if (n == (long)ND * NQKV)   Wqkv = (const float*)d_in[i];
        else if (n == (long)ND * ND)     Wout = (const float*)d_in[i];
    }
    float* out = (float*)d_out;

    cudaFuncSetAttribute(gemm_mma_kernel<0>, cudaFuncAttributeMaxDynamicSharedMemorySize, GEMM_SMEM);
    cudaFuncSetAttribute(gemm_mma_kernel<1>, cudaFuncAttributeMaxDynamicSharedMemorySize, GEMM_SMEM);
    cudaFuncSetAttribute(attn_mma_kernel, cudaFuncAttributeMaxDynamicSharedMemorySize, ATTN_SMEM);

    // Fused tf32 pre-round pass
    conv_all_kernel<<<NCONV4 / 256, 256>>>(xs, Wqkv, Wout);

    // QKV projection: [4096,768] @ [768,2304], scatter epilogue
    gemm_mma_kernel<0><<<dim3(NQKV / 128, M_ROWS / 128), 256, GEMM_SMEM>>>(out);

    // Flash attention (tf32 mma, 64-q blocks, 4 CTAs/SM)
    attn_mma_kernel<<<dim3(NS / 64, BHN), 128, ATTN_SMEM>>>();

    // Output projection: [4096,768] @ [768,768] -> d_out
    gemm_mma_kernel<1><<<dim3(ND / 128, M_ROWS / 128), 256, GEMM_SMEM>>>(out);
}